// round 6
// baseline (speedup 1.0000x reference)
#include <cuda_runtime.h>
#include <cuda_bf16.h>
#include <stdint.h>

#define NN 50000
#define EE 600000
#define Hh 128
#define EDdim 16
#define Bb 256
#define Ll 5
#define NBLK 196                    // ceil(NN/256)
#define GBLK ((NN + 127) / 128)     // 391 GEMM CTAs
#define STRIDE 136                  // padded bf16 row stride in smem
#define BLO_ELEM (128 * STRIDE)     // lo-plane offset in bf16 elems
#define GEMM_SMEM (2 * 128 * STRIDE * 2)   // B hi+lo only: 69,632 bytes

// ======================= device scratch =======================
__device__ float g_x[(size_t)NN * Hh];
__device__ float g_h[(size_t)NN * Hh];
__device__ float g_agg[(size_t)NN * Hh];
__device__ float g_eagg[(size_t)NN * EDdim];
__device__ int   g_deg[NN];
__device__ int   g_rowptr[NN + 1];
__device__ int   g_cursor[NN];
__device__ int   g_srcA[EE];
__device__ int   g_eidA[EE];
__device__ int   g_bsum[NBLK];
__device__ int   g_boff[NBLK];
__device__ float g_counts[Bb];
__device__ float g_pooled[Bb * Hh];
__device__ float g_vn[Bb * Hh];
__device__ __nv_bfloat16 g_whi[15 * Hh * Hh];  // [mat][n][k] transposed split
__device__ __nv_bfloat16 g_wlo[15 * Hh * Hh];

// ======================= preprocessing =======================
__global__ void k_wsplit(const float* __restrict__ nodeW, const float* __restrict__ m1W,
                         const float* __restrict__ m2W) {
    int b = blockIdx.x;
    int mat = b >> 6;
    int idx = ((b & 63) << 8) + threadIdx.x;   // 0..16383 over [n][k]
    const float* Wsrc = (mat < 5) ? (nodeW + (size_t)mat * Hh * Hh)
                      : (mat < 10) ? (m1W + (size_t)(mat - 5) * Hh * Hh)
                      : (m2W + (size_t)(mat - 10) * Hh * Hh);
    int n = idx >> 7, k = idx & 127;
    float w = Wsrc[k * Hh + n];
    __nv_bfloat16 hi = __float2bfloat16(w);
    __nv_bfloat16 lo = __float2bfloat16(w - __bfloat162float(hi));
    g_whi[(size_t)mat * Hh * Hh + idx] = hi;
    g_wlo[(size_t)mat * Hh * Hh + idx] = lo;
}

__global__ void k_vn_init(const float* __restrict__ vninit) {
    g_vn[blockIdx.x * Hh + threadIdx.x] = vninit[threadIdx.x];
}

__global__ void k_counts(const int* __restrict__ batch) {
    int i = blockIdx.x * 256 + threadIdx.x;
    if (i < NN) atomicAdd(&g_counts[batch[i]], 1.0f);
}

__global__ void k_deg(const int* __restrict__ dst) {
    int e = blockIdx.x * 256 + threadIdx.x;
    if (e < EE) atomicAdd(&g_deg[dst[e]], 1);
}

__global__ void k_bsum() {
    __shared__ int s[256];
    int t = threadIdx.x;
    int i = blockIdx.x * 256 + t;
    s[t] = (i < NN) ? g_deg[i] : 0;
    __syncthreads();
    for (int o = 128; o > 0; o >>= 1) {
        if (t < o) s[t] += s[t + o];
        __syncthreads();
    }
    if (t == 0) g_bsum[blockIdx.x] = s[0];
}

__global__ void k_bscan() {
    __shared__ int s[256];
    int t = threadIdx.x;
    int v = (t < NBLK) ? g_bsum[t] : 0;
    s[t] = v;
    __syncthreads();
    for (int o = 1; o < 256; o <<= 1) {
        int u = (t >= o) ? s[t - o] : 0;
        __syncthreads();
        s[t] += u;
        __syncthreads();
    }
    if (t < NBLK) g_boff[t] = s[t] - v;
    if (t == 255) g_rowptr[NN] = s[255];
}

__global__ void k_bfill() {
    __shared__ int s[256];
    int t = threadIdx.x;
    int i = blockIdx.x * 256 + t;
    int v = (i < NN) ? g_deg[i] : 0;
    s[t] = v;
    __syncthreads();
    for (int o = 1; o < 256; o <<= 1) {
        int u = (t >= o) ? s[t - o] : 0;
        __syncthreads();
        s[t] += u;
        __syncthreads();
    }
    if (i < NN) {
        int pos = g_boff[blockIdx.x] + s[t] - v;
        g_rowptr[i] = pos;
        g_cursor[i] = pos;
    }
}

__global__ void k_fill(const int* __restrict__ src, const int* __restrict__ dst) {
    int e = blockIdx.x * 256 + threadIdx.x;
    if (e >= EE) return;
    int d = dst[e];
    int pos = atomicAdd(&g_cursor[d], 1);
    g_srcA[pos] = src[e];
    g_eidA[pos] = e;
}

__global__ void k_eagg(const float* __restrict__ eattr) {
    int w = (blockIdx.x * 256 + threadIdx.x) >> 5;
    int lane = threadIdx.x & 31;
    if (w >= NN || lane >= EDdim) return;
    int beg = g_rowptr[w], end = g_rowptr[w + 1];
    float s = 0.f;
    for (int e = beg; e < end; e++) {
        int eid = g_eidA[e];
        s += eattr[(size_t)eid * EDdim + lane];
    }
    g_eagg[w * EDdim + lane] = s;
}

// ======================= HMMA bf16-split GEMM v3 (32x64 warp tile) =======================
// C[M,128] = A[M,128] @ W[128,128]; D = Ahi@Bhi + Ahi@Blo + Alo@Bhi (fp32 accum).
// Warp grid 4(rows)x2(cols): each warp 32 rows x 64 cols.
// EPI 0: +bias +vn[batch]; EPI 1: relu(+bias); EPI 2: relu(+bias) + pooled atomic.

__device__ __forceinline__ void mma16816(float* c, uint32_t a0, uint32_t a1, uint32_t a2,
                                         uint32_t a3, uint32_t b0, uint32_t b1) {
    asm volatile(
        "mma.sync.aligned.m16n8k16.row.col.f32.bf16.bf16.f32 "
        "{%0,%1,%2,%3}, {%4,%5,%6,%7}, {%8,%9}, {%0,%1,%2,%3};"
        : "+f"(c[0]), "+f"(c[1]), "+f"(c[2]), "+f"(c[3])
        : "r"(a0), "r"(a1), "r"(a2), "r"(a3), "r"(b0), "r"(b1));
}

#define LDSM4(r0, r1, r2, r3, addr) \
    asm volatile("ldmatrix.sync.aligned.m8n8.x4.shared.b16 {%0,%1,%2,%3}, [%4];" \
                 : "=r"(r0), "=r"(r1), "=r"(r2), "=r"(r3) : "r"(addr))

__device__ __forceinline__ uint32_t smem_to_u32(const void* p) {
    uint32_t a;
    asm("{ .reg .u64 t; cvta.to.shared.u64 t, %1; cvt.u32.u64 %0, t; }" : "=r"(a) : "l"(p));
    return a;
}

// pack float2 (v.x = even k, v.y = odd k) into bf16x2 hi + residual lo words
__device__ __forceinline__ void packsplit(float2 v, uint32_t& h, uint32_t& l) {
    uint32_t hp;
    asm("cvt.rn.bf16x2.f32 %0, %1, %2;" : "=r"(hp) : "f"(v.y), "f"(v.x));
    float h0 = __uint_as_float(hp << 16);
    float h1 = __uint_as_float(hp & 0xffff0000u);
    uint32_t lp;
    asm("cvt.rn.bf16x2.f32 %0, %1, %2;" : "=r"(lp) : "f"(v.y - h1), "f"(v.x - h0));
    h = hp;
    l = lp;
}

template <int EPI>
__launch_bounds__(256, 2)
__global__ void gemm_tc(const float* __restrict__ A, const __nv_bfloat16* __restrict__ Whi,
                        const __nv_bfloat16* __restrict__ Wlo, const float* __restrict__ bias,
                        float* __restrict__ C, const int* __restrict__ batch,
                        const float* __restrict__ vn, float* __restrict__ pooled, int M) {
    extern __shared__ __nv_bfloat16 sm[];
    const int tid = threadIdx.x;
    const int wid = tid >> 5;
    const int lane = tid & 31;
    const int tb = blockIdx.x * 128;

    // ---- stage pre-split W [n][k] into smem (hi plane + lo plane) ----
#pragma unroll
    for (int it = 0; it < 8; it++) {
        int idx = it * 256 + tid;
        int n = idx >> 4;
        int k8 = (idx & 15) << 3;
        uint4 hv = *(const uint4*)(Whi + (size_t)n * Hh + k8);
        uint4 lv = *(const uint4*)(Wlo + (size_t)n * Hh + k8);
        *(uint4*)&sm[n * STRIDE + k8] = hv;
        *(uint4*)&sm[BLO_ELEM + n * STRIDE + k8] = lv;
    }

    // ---- per-thread fragment geometry ----
    const int wr = wid & 3;             // row band (x32 rows)
    const int wc = wid >> 2;            // col half (x64 cols)
    const int g = lane >> 2;
    const int tig = lane & 3;

    int grow[4];
    bool gv[4];
    const float* Ap[4];
#pragma unroll
    for (int j = 0; j < 4; j++) {
        grow[j] = tb + wr * 32 + j * 8 + g;
        gv[j] = grow[j] < M;
        Ap[j] = A + (size_t)(gv[j] ? grow[j] : 0) * Hh + 2 * tig;
    }

    // ldmatrix per-thread row address component (within a 16-col x 16-k block)
    const int mq = lane >> 3;           // 0..3 (matrix select)
    const int tr = lane & 7;
    const uint32_t smem_u32 = smem_to_u32(sm);
    const uint32_t brow_off = (uint32_t)((((mq >> 1) * 8 + tr) * STRIDE + (mq & 1) * 8) * 2);
    const uint32_t colb = (uint32_t)(wc * 64 * STRIDE * 2);   // byte offset of warp's col half

    float c[2][8][4];
#pragma unroll
    for (int m = 0; m < 2; m++)
#pragma unroll
        for (int n = 0; n < 8; n++)
#pragma unroll
            for (int j = 0; j < 4; j++) c[m][n][j] = 0.f;

    // prefetch k=0 A fragments (fp32): pa[j][0] = (row j, k0+2tig), pa[j][1] = (row j, k0+8+2tig)
    float2 pa[4][2];
#pragma unroll
    for (int j = 0; j < 4; j++) {
        pa[j][0] = *(const float2*)(Ap[j]);
        pa[j][1] = *(const float2*)(Ap[j] + 8);
    }

    __syncthreads();

#pragma unroll 1
    for (int k = 0; k < 8; k++) {
        // build A fragments for both m-tiles (rows j=0,1 -> m0; j=2,3 -> m1)
        uint32_t ahA[4], alA[4], ahB[4], alB[4];
#pragma unroll
        for (int j = 0; j < 4; j++) {
            packsplit(pa[j][0], ahA[j], alA[j]);
            packsplit(pa[j][1], ahB[j], alB[j]);
        }
        if (k < 7) {
            int off = (k + 1) << 4;
#pragma unroll
            for (int j = 0; j < 4; j++) {
                pa[j][0] = *(const float2*)(Ap[j] + off);
                pa[j][1] = *(const float2*)(Ap[j] + off + 8);
            }
        }
        const uint32_t kb = smem_u32 + brow_off + colb + ((uint32_t)k << 5);
#pragma unroll
        for (int n2 = 0; n2 < 4; n2++) {
            uint32_t ha = kb + (uint32_t)(n2 * 16 * STRIDE * 2);
            uint32_t la = ha + BLO_ELEM * 2;
            uint32_t bh0, bh1, bh2, bh3, bl0, bl1, bl2, bl3;
            LDSM4(bh0, bh1, bh2, bh3, ha);
            LDSM4(bl0, bl1, bl2, bl3, la);
#pragma unroll
            for (int m = 0; m < 2; m++) {
                uint32_t a0 = ahA[2 * m], a1 = ahA[2 * m + 1];
                uint32_t a2 = ahB[2 * m], a3 = ahB[2 * m + 1];
                uint32_t q0 = alA[2 * m], q1 = alA[2 * m + 1];
                uint32_t q2 = alB[2 * m], q3 = alB[2 * m + 1];
                mma16816(c[m][2 * n2], a0, a1, a2, a3, bh0, bh1);
                mma16816(c[m][2 * n2], a0, a1, a2, a3, bl0, bl1);
                mma16816(c[m][2 * n2], q0, q1, q2, q3, bh0, bh1);
                mma16816(c[m][2 * n2 + 1], a0, a1, a2, a3, bh2, bh3);
                mma16816(c[m][2 * n2 + 1], a0, a1, a2, a3, bl2, bl3);
                mma16816(c[m][2 * n2 + 1], q0, q1, q2, q3, bh2, bh3);
            }
        }
    }

    // ---- epilogue ----
    int gc[4] = {0, 0, 0, 0};
    if (EPI == 0 || EPI == 2) {
#pragma unroll
        for (int j = 0; j < 4; j++)
            if (gv[j]) gc[j] = batch[grow[j]];
    }
#pragma unroll
    for (int m = 0; m < 2; m++) {
        int j0 = 2 * m, j1 = 2 * m + 1;
#pragma unroll
        for (int n = 0; n < 8; n++) {
            int col = wc * 64 + (n << 3) + 2 * tig;
            float2 bv = *(const float2*)(bias + col);
            float o0x = c[m][n][0] + bv.x, o0y = c[m][n][1] + bv.y;
            float o1x = c[m][n][2] + bv.x, o1y = c[m][n][3] + bv.y;
            if (EPI == 0) {
                if (gv[j0]) {
                    float2 vv = *(const float2*)(vn + gc[j0] * Hh + col);
                    o0x += vv.x; o0y += vv.y;
                }
                if (gv[j1]) {
                    float2 vv = *(const float2*)(vn + gc[j1] * Hh + col);
                    o1x += vv.x; o1y += vv.y;
                }
            } else {
                o0x = fmaxf(o0x, 0.f); o0y = fmaxf(o0y, 0.f);
                o1x = fmaxf(o1x, 0.f); o1y = fmaxf(o1y, 0.f);
            }
            if (gv[j0]) {
                *(float2*)(C + (size_t)grow[j0] * Hh + col) = make_float2(o0x, o0y);
                if (EPI == 2) {
                    atomicAdd(&pooled[gc[j0] * Hh + col], o0x);
                    atomicAdd(&pooled[gc[j0] * Hh + col + 1], o0y);
                }
            }
            if (gv[j1]) {
                *(float2*)(C + (size_t)grow[j1] * Hh + col) = make_float2(o1x, o1y);
                if (EPI == 2) {
                    atomicAdd(&pooled[gc[j1] * Hh + col], o1x);
                    atomicAdd(&pooled[gc[j1] * Hh + col + 1], o1y);
                }
            }
        }
    }
}

// ======================= SpMM =======================
__launch_bounds__(256)
__global__ void spmm(const float* __restrict__ h, const float* __restrict__ eW,
                     const float* __restrict__ eb, float* __restrict__ agg) {
    __shared__ float sW[EDdim * Hh];
    for (int i = threadIdx.x; i < EDdim * Hh; i += 256) sW[i] = eW[i];
    __syncthreads();
    int warp = (blockIdx.x * 256 + threadIdx.x) >> 5;
    int lane = threadIdx.x & 31;
    if (warp >= NN) return;
    const int row = warp;
    const int c4 = lane << 2;

    float4 acc = make_float4(0.f, 0.f, 0.f, 0.f);
    const float* ea = g_eagg + row * EDdim;
#pragma unroll
    for (int k = 0; k < EDdim; k++) {
        float v = ea[k];
        float4 w = *(const float4*)&sW[k * Hh + c4];
        acc.x = fmaf(v, w.x, acc.x);
        acc.y = fmaf(v, w.y, acc.y);
        acc.z = fmaf(v, w.z, acc.z);
        acc.w = fmaf(v, w.w, acc.w);
    }
    int beg = g_rowptr[row];
    int end = g_rowptr[row + 1];
    float degf = (float)(end - beg);
    float4 bb = *(const float4*)(eb + c4);
    acc.x = fmaf(degf, bb.x, acc.x);
    acc.y = fmaf(degf, bb.y, acc.y);
    acc.z = fmaf(degf, bb.z, acc.z);
    acc.w = fmaf(degf, bb.w, acc.w);

    int e = beg;
    for (; e + 1 < end; e += 2) {
        int s0 = g_srcA[e];
        int s1 = g_srcA[e + 1];
        float4 h0 = *(const float4*)(h + (size_t)s0 * Hh + c4);
        float4 h1 = *(const float4*)(h + (size_t)s1 * Hh + c4);
        acc.x += h0.x + h1.x;
        acc.y += h0.y + h1.y;
        acc.z += h0.z + h1.z;
        acc.w += h0.w + h1.w;
    }
    if (e < end) {
        int s0 = g_srcA[e];
        float4 h0 = *(const float4*)(h + (size_t)s0 * Hh + c4);
        acc.x += h0.x;
        acc.y += h0.y;
        acc.z += h0.z;
        acc.w += h0.w;
    }
    *(float4*)(agg + (size_t)row * Hh + c4) = acc;
}

// ======================= small dense tails =======================
__global__ void vn_update(const float* __restrict__ w0, const float* __restrict__ b0,
                          const float* __restrict__ w1, const float* __restrict__ b1) {
    __shared__ float p[Hh];
    __shared__ float r0[Hh];
    int g = blockIdx.x, j = threadIdx.x;
    float cnt = fmaxf(g_counts[g], 1.f);
    p[j] = g_pooled[g * Hh + j] / cnt;
    __syncthreads();
    float s = b0[j];
    for (int k = 0; k < Hh; k++) s = fmaf(p[k], w0[k * Hh + j], s);
    r0[j] = fmaxf(s, 0.f);
    __syncthreads();
    float s2 = b1[j];
    for (int k = 0; k < Hh; k++) s2 = fmaf(r0[k], w1[k * Hh + j], s2);
    g_vn[g * Hh + j] += fmaxf(s2, 0.f);
}

__global__ void final_fc(const float* __restrict__ fcW, const float* __restrict__ fcb,
                         float* __restrict__ out) {
    __shared__ float p[Hh];
    int g = blockIdx.x, j = threadIdx.x;
    float cnt = fmaxf(g_counts[g], 1.f);
    p[j] = g_pooled[g * Hh + j] / cnt;
    __syncthreads();
    float s = fcb[j];
    for (int k = 0; k < Hh; k++) s = fmaf(p[k], fcW[k * Hh + j], s);
    out[g * Hh + j] = s;
}

// ======================= launch =======================
extern "C" void kernel_launch(void* const* d_in, const int* in_sizes, int n_in,
                              void* d_out, int out_size) {
    const float* x      = (const float*)d_in[0];
    const float* eattr  = (const float*)d_in[1];
    const float* nodeW  = (const float*)d_in[2];
    const float* nodeB  = (const float*)d_in[3];
    const float* edgeW  = (const float*)d_in[4];
    const float* edgeB  = (const float*)d_in[5];
    const float* m1W    = (const float*)d_in[6];
    const float* m1B    = (const float*)d_in[7];
    const float* m2W    = (const float*)d_in[8];
    const float* m2B    = (const float*)d_in[9];
    const float* vnw0   = (const float*)d_in[10];
    const float* vnb0   = (const float*)d_in[11];
    const float* vnw1   = (const float*)d_in[12];
    const float* vnb1   = (const float*)d_in[13];
    const float* fcW    = (const float*)d_in[14];
    const float* fcB    = (const float*)d_in[15];
    const float* vninit = (const float*)d_in[16];
    const int*   eidx   = (const int*)d_in[17];
    const int*   batch  = (const int*)d_in[18];
    const int* srcp = eidx;
    const int* dstp = eidx + EE;
    float* out = (float*)d_out;

    void *p_deg, *p_counts, *p_pooled, *p_x, *p_h, *p_agg, *p_vn, *p_whi, *p_wlo;
    cudaGetSymbolAddress(&p_deg, g_deg);
    cudaGetSymbolAddress(&p_counts, g_counts);
    cudaGetSymbolAddress(&p_pooled, g_pooled);
    cudaGetSymbolAddress(&p_x, g_x);
    cudaGetSymbolAddress(&p_h, g_h);
    cudaGetSymbolAddress(&p_agg, g_agg);
    cudaGetSymbolAddress(&p_vn, g_vn);
    cudaGetSymbolAddress(&p_whi, g_whi);
    cudaGetSymbolAddress(&p_wlo, g_wlo);

    cudaFuncSetAttribute(gemm_tc<0>, cudaFuncAttributeMaxDynamicSharedMemorySize, GEMM_SMEM);
    cudaFuncSetAttribute(gemm_tc<1>, cudaFuncAttributeMaxDynamicSharedMemorySize, GEMM_SMEM);
    cudaFuncSetAttribute(gemm_tc<2>, cudaFuncAttributeMaxDynamicSharedMemorySize, GEMM_SMEM);

    const __nv_bfloat16* whi = (const __nv_bfloat16*)p_whi;
    const __nv_bfloat16* wlo = (const __nv_bfloat16*)p_wlo;

    // launches 1..5 (memsets count), so first GEMM is #6 for the ncu window
    cudaMemsetAsync(p_deg, 0, sizeof(int) * NN);           // 1
    cudaMemsetAsync(p_counts, 0, sizeof(float) * Bb);      // 2
    k_wsplit<<<960, 256>>>(nodeW, m1W, m2W);               // 3
    k_vn_init<<<Bb, Hh>>>(vninit);                         // 4
    k_counts<<<(NN + 255) / 256, 256>>>(batch);            // 5
    gemm_tc<0><<<GBLK, 256, GEMM_SMEM>>>(x, whi, wlo, nodeB,   // 6  <- profiled
                                         (float*)p_h, batch, (const float*)p_vn, nullptr, NN);

    // CSR build (independent of gemm0)
    k_deg<<<(EE + 255) / 256, 256>>>(dstp);
    k_bsum<<<NBLK, 256>>>();
    k_bscan<<<1, 256>>>();
    k_bfill<<<NBLK, 256>>>();
    k_fill<<<(EE + 255) / 256, 256>>>(srcp, dstp);
    k_eagg<<<(NN + 7) / 8, 256>>>(eattr);

    const int SPB = (NN + 7) / 8;

    for (int l = 0; l < Ll; l++) {
        if (l > 0) {
            gemm_tc<0><<<GBLK, 256, GEMM_SMEM>>>((const float*)p_x, whi + (size_t)l * Hh * Hh,
                                                 wlo + (size_t)l * Hh * Hh, nodeB + l * Hh,
                                                 (float*)p_h, batch, (const float*)p_vn, nullptr, NN);
        }
        spmm<<<SPB, 256>>>((const float*)p_h, edgeW + (size_t)l * EDdim * Hh,
                           edgeB + l * Hh, (float*)p_agg);
        cudaMemsetAsync(p_pooled, 0, sizeof(float) * Bb * Hh);
        gemm_tc<1><<<GBLK, 256, GEMM_SMEM>>>((const float*)p_agg, whi + (size_t)(5 + l) * Hh * Hh,
                                             wlo + (size_t)(5 + l) * Hh * Hh, m1B + l * Hh,
                                             (float*)p_h, nullptr, nullptr, nullptr, NN);
        gemm_tc<2><<<GBLK, 256, GEMM_SMEM>>>((const float*)p_h, whi + (size_t)(10 + l) * Hh * Hh,
                                             wlo + (size_t)(10 + l) * Hh * Hh, m2B + l * Hh,
                                             (float*)p_x, batch, nullptr, (float*)p_pooled, NN);
        if (l < Ll - 1) vn_update<<<Bb, Hh>>>(vnw0, vnb0, vnw1, vnb1);
    }
    final_fc<<<Bb, Hh>>>(fcW, fcB, out);
}